// round 15
// baseline (speedup 1.0000x reference)
#include <cuda_runtime.h>
#include <cuda_fp16.h>
#include <math.h>

#define TLEN 32768
#define NF   65536
#define TWO_PI 6.283185307179586476925f

// 128 complex signals x 65536 points, fp16 (re,im) packed = 32 MB scratch.
// Layout: g_work[p][k1*4096 + t1*256 + t]
__device__ __half2 g_work[128 * 65536];
// filter intermediate (fp32, after K1 filter branch, same layout as g_work)
__device__ float2 g_filt[65536];
// final filter spectrum (fp16, K2-register-matched, includes 1/65536)
__device__ __half2 g_wf[65536];

__device__ __forceinline__ float2 cmul(float2 a, float2 b) {
    return make_float2(fmaf(a.x, b.x, -(a.y * b.y)), fmaf(a.x, b.y, a.y * b.x));
}
__device__ __forceinline__ __half2 pack_h2(float2 a) { return __floats2half2_rn(a.x, a.y); }
__device__ __forceinline__ float2 unpack_h2(__half2 h) {
    float2 f = __half22float2(h);
    return make_float2(f.x, f.y);
}

// packed f32x2 add/sub (Blackwell): 1 instruction for a complex add/sub
__device__ __forceinline__ float2 f2add(float2 a, float2 b) {
    float2 c;
    asm("{\n\t.reg .b64 ra, rb, rc;\n\t"
        "mov.b64 ra, {%2, %3};\n\t"
        "mov.b64 rb, {%4, %5};\n\t"
        "add.rn.f32x2 rc, ra, rb;\n\t"
        "mov.b64 {%0, %1}, rc;\n\t}"
        : "=f"(c.x), "=f"(c.y)
        : "f"(a.x), "f"(a.y), "f"(b.x), "f"(b.y));
    return c;
}
__device__ __forceinline__ float2 f2sub(float2 a, float2 b) {
    float2 c;
    asm("{\n\t.reg .b64 ra, rb, rc;\n\t"
        "mov.b64 ra, {%2, %3};\n\t"
        "mov.b64 rb, {%4, %5};\n\t"
        "sub.rn.f32x2 rc, ra, rb;\n\t"
        "mov.b64 {%0, %1}, rc;\n\t}"
        : "=f"(c.x), "=f"(c.y)
        : "f"(a.x), "f"(a.y), "f"(b.x), "f"(b.y));
    return c;
}

template<int SIGN>
__device__ __forceinline__ void fft4(float2& a0, float2& a1, float2& a2, float2& a3) {
    float2 s0 = f2add(a0, a2);
    float2 d0 = f2sub(a0, a2);
    float2 s1 = f2add(a1, a3);
    float2 d1 = f2sub(a1, a3);
    float2 wd1 = (SIGN < 0) ? make_float2(d1.y, -d1.x) : make_float2(-d1.y, d1.x);
    a0 = f2add(s0, s1);
    a2 = f2sub(s0, s1);
    a1 = f2add(d0, wd1);
    a3 = f2sub(d0, wd1);
}

template<int SIGN>
__device__ __forceinline__ float2 w16f(int m) {
    const float C[10] = {1.f, 0.92387953251128675613f, 0.70710678118654752440f,
                         0.38268343236508977173f, 0.f, -0.38268343236508977173f,
                         -0.70710678118654752440f, -0.92387953251128675613f,
                         -1.f, -0.92387953251128675613f};
    const float S[10] = {0.f, 0.38268343236508977173f, 0.70710678118654752440f,
                         0.92387953251128675613f, 1.f, 0.92387953251128675613f,
                         0.70710678118654752440f, 0.38268343236508977173f,
                         0.f, -0.38268343236508977173f};
    return make_float2(C[m], (SIGN < 0) ? -S[m] : S[m]);
}

// 16-point DFT, natural-order in/out
template<int SIGN>
__device__ __forceinline__ void fft16(float2 v[16]) {
    #pragma unroll
    for (int b = 0; b < 4; b++) fft4<SIGN>(v[b], v[4 + b], v[8 + b], v[12 + b]);
    #pragma unroll
    for (int p = 1; p < 4; p++) {
        #pragma unroll
        for (int b = 1; b < 4; b++)
            v[4 * p + b] = cmul(v[4 * p + b], w16f<SIGN>(b * p));
    }
    #pragma unroll
    for (int p = 0; p < 4; p++) fft4<SIGN>(v[4 * p + 0], v[4 * p + 1], v[4 * p + 2], v[4 * p + 3]);
    float2 o[16];
    #pragma unroll
    for (int q = 0; q < 4; q++)
        #pragma unroll
        for (int p = 0; p < 4; p++) o[4 * q + p] = v[4 * p + q];
    #pragma unroll
    for (int i = 0; i < 16; i++) v[i] = o[i];
}

// v[k] *= t0 * w^k for k = 0..15, via 4 independent chains of 4 (log depth).
// UNIT=true: t0 == 1 (skips setup products and the v[0] multiply).
template<bool UNIT>
__device__ __forceinline__ void twmul16(float2 v[16], float2 t0, float2 w) {
    float2 t2 = cmul(w, w);
    float2 t4 = cmul(t2, t2);
    float2 t8 = cmul(t4, t4);
    float2 a, b, c, d;
    if (UNIT) { a = make_float2(1.f, 0.f); b = t4; c = t8; d = cmul(t4, t8); }
    else      { a = t0; b = cmul(t0, t4); c = cmul(t0, t8); d = cmul(b, t8); }
    #pragma unroll
    for (int i = 0; i < 4; i++) {
        if (!(UNIT && i == 0)) v[i] = cmul(v[i], a);
        v[4 + i]  = cmul(v[4 + i], b);
        v[8 + i]  = cmul(v[8 + i], c);
        v[12 + i] = cmul(v[12 + i], d);
        if (i < 3) {
            a = (UNIT && i == 0) ? w : cmul(a, w);
            b = cmul(b, w); c = cmul(c, w); d = cmul(d, w);
        }
    }
}

// 256-point DFT within one half-warp (group g = t>>4, lane l = t&15).
// wc = e^{SIGN*2pi i l/256} supplied by the caller (hoistable).
// Warp-private exchange (pad-17): write k1*17+l, read l*17+n2 — conflict-free.
template<int SIGN>
__device__ __forceinline__ void fft256_core(float2 v[16], int l, int g,
                                            float2* sh, float2 wc) {
    fft16<SIGN>(v);
    twmul16<true>(v, make_float2(1.f, 0.f), wc);
    __syncwarp();
    #pragma unroll
    for (int k1 = 0; k1 < 16; k1++)
        sh[g * 272 + k1 * 17 + l] = v[k1];
    __syncwarp();
    #pragma unroll
    for (int n2 = 0; n2 < 16; n2++)
        v[n2] = sh[g * 272 + l * 17 + n2];
    fft16<SIGN>(v);
}

// ======== K1 (persistent): column fft16 + interstage twiddle + row stage-1
// fft16 + T1 twiddle. Tiles 0..2047: signals; 2048..2063: filter. ========
__global__ void __launch_bounds__(256, 5) k_colA(const float* __restrict__ x,
                                                 const float* __restrict__ f) {
    __shared__ float2 sh[16 * 272];
    int t = threadIdx.x;
    int hi = t >> 4, tl = t & 15;
    for (int tile = blockIdx.x; tile < 2064; tile += gridDim.x) {
        bool is_filt = (tile >= 2048);
        int p = 0, tb;
        if (is_filt) tb = tile - 2048;
        else { p = tile >> 4; tb = tile & 15; }
        int tcol = tb * 16 + tl;
        int n2 = hi * 256 + tcol;         // phase 1: hi = a
        float2 v[16];
        if (!is_filt) {
            const float* xr = x + (size_t)(2 * p) * TLEN;
            const float* xi = x + (size_t)(2 * p + 1) * TLEN;
            #pragma unroll
            for (int n1 = 0; n1 < 16; n1++) {
                if (n1 < 8) v[n1] = make_float2(xr[n1 * 4096 + n2], xi[n1 * 4096 + n2]);
                else v[n1] = make_float2(0.f, 0.f);
            }
        } else {
            #pragma unroll
            for (int n1 = 0; n1 < 16; n1++) {
                if (n1 < 8) v[n1] = make_float2(f[n1 * 4096 + n2], 0.f);
                else v[n1] = make_float2(0.f, 0.f);
            }
        }
        fft16<-1>(v);  // over n1 -> v[k1]
        // interstage twiddle e^{-2pi i n2 k1 / 65536}
        { float s, c; __sincosf(-TWO_PI * (float)n2 / 65536.0f, &s, &c);
          twmul16<true>(v, make_float2(1.f, 0.f), make_float2(c, s)); }
        // RT: (a, tl) holding all k1  ->  (k1, tl) holding all a
        #pragma unroll
        for (int k1 = 0; k1 < 16; k1++)
            sh[k1 * 272 + hi * 17 + tl] = v[k1];
        __syncthreads();
        #pragma unroll
        for (int a = 0; a < 16; a++)
            v[a] = sh[hi * 272 + a * 17 + tl];   // now hi = k1
        fft16<-1>(v);  // row stage-1 over a -> v[t1]
        // T1 twiddle e^{-2pi i tcol t1 / 4096}
        { float s, c; __sincosf(-TWO_PI * (float)tcol / 4096.0f, &s, &c);
          twmul16<true>(v, make_float2(1.f, 0.f), make_float2(c, s)); }
        if (!is_filt) {
            __half2* dst = g_work + (size_t)p * NF + hi * 4096;
            #pragma unroll
            for (int t1 = 0; t1 < 16; t1++)
                dst[t1 * 256 + tcol] = pack_h2(v[t1]);
        } else {
            float2* dst = g_filt + hi * 4096;
            #pragma unroll
            for (int t1 = 0; t1 < 16; t1++)
                dst[t1 * 256 + tcol] = v[t1];
        }
        __syncthreads();  // WAR: protect sh before next tile
    }
}

// ======== K0b: filter 256-pt row FFT -> fp16 wf (K2-matched, x 1/65536) ========
__global__ void __launch_bounds__(256) k_filt_rowB() {
    __shared__ float2 sh[16 * 272];
    int t = threadIdx.x;
    int g = t >> 4, l = t & 15;
    int k1 = blockIdx.x;
    float sv, cv; __sincosf(-TWO_PI * (float)l / 256.0f, &sv, &cv);
    const float2* basef = g_filt + k1 * 4096;
    float2 v[16];
    #pragma unroll
    for (int j = 0; j < 16; j++)
        v[j] = basef[g * 256 + 16 * j + l];
    fft256_core<-1>(v, l, g, sh, make_float2(cv, sv));
    const float inv = 1.0f / 65536.0f;
    #pragma unroll
    for (int u2 = 0; u2 < 16; u2++)
        g_wf[k1 * 4096 + u2 * 256 + t] =
            pack_h2(make_float2(v[u2].x * inv, v[u2].y * inv));
}

// ======== K2 (persistent): 256-pt fwd -> *Wf -> 256-pt inv. Warp-local. ======
__global__ void __launch_bounds__(256, 4) k_rowB() {
    __shared__ float2 sh[16 * 272];
    int t = threadIdx.x;
    int g = t >> 4, l = t & 15;
    float sv, cv; __sincosf(-TWO_PI * (float)l / 256.0f, &sv, &cv);
    float2 wfw = make_float2(cv, sv);    // forward core twiddle base
    float2 wiv = make_float2(cv, -sv);   // inverse core twiddle base (conj)
    for (int tile = blockIdx.x; tile < 2048; tile += gridDim.x) {
        int p = tile >> 4, k1 = tile & 15;
        __half2* base = g_work + (size_t)p * NF + k1 * 4096;
        const __half2* __restrict__ wfh = g_wf + k1 * 4096;
        float2 v[16];
        #pragma unroll
        for (int j = 0; j < 16; j++)
            v[j] = unpack_h2(base[g * 256 + 16 * j + l]);
        fft256_core<-1>(v, l, g, sh, wfw);
        #pragma unroll
        for (int u2 = 0; u2 < 16; u2++)
            v[u2] = cmul(v[u2], unpack_h2(wfh[u2 * 256 + t]));
        fft256_core<1>(v, l, g, sh, wiv);
        #pragma unroll
        for (int sg = 0; sg < 16; sg++)
            base[g * 256 + 16 * sg + l] = pack_h2(v[sg]);
    }
}

// ======== K3 (persistent): undo-T1 + row stage-1 inverse fft16 + conj
// interstage + column inverse fft16 + write y ========
__global__ void __launch_bounds__(256, 5) k_colA_inv(float* __restrict__ y) {
    __shared__ float2 sh[16 * 272];
    int t = threadIdx.x;
    int hi = t >> 4, tl = t & 15;
    for (int tile = blockIdx.x; tile < 2048; tile += gridDim.x) {
        int p = tile >> 4, tb = tile & 15;
        int tcol = tb * 16 + tl;
        const __half2* src = g_work + (size_t)p * NF;
        float2 v[16];
        #pragma unroll
        for (int t1 = 0; t1 < 16; t1++)
            v[t1] = unpack_h2(src[hi * 4096 + t1 * 256 + tcol]);   // hi = k1
        // undo T1: e^{+2pi i tcol t1 / 4096}
        { float s, c; __sincosf(TWO_PI * (float)tcol / 4096.0f, &s, &c);
          twmul16<true>(v, make_float2(1.f, 0.f), make_float2(c, s)); }
        fft16<1>(v);  // over t1 -> v[a] = z_row[a*256 + tcol]
        // conj interstage: omegaN^{+(a*256+tcol)*k1} over a
        { float s0, c0; __sincosf(TWO_PI * (float)(tcol * hi) / 65536.0f, &s0, &c0);
          float sw, cw; __sincosf(TWO_PI * (float)hi / 256.0f, &sw, &cw);
          twmul16<false>(v, make_float2(c0, s0), make_float2(cw, sw)); }
        // RT: (k1, tl) holding all a  ->  (a, tl) holding all k1
        #pragma unroll
        for (int a = 0; a < 16; a++)
            sh[a * 272 + hi * 17 + tl] = v[a];
        __syncthreads();
        #pragma unroll
        for (int k1 = 0; k1 < 16; k1++)
            v[k1] = sh[hi * 272 + k1 * 17 + tl];   // now hi = a
        fft16<1>(v);  // over k1 -> v[n1]
        float* yr = y + (size_t)(2 * p) * TLEN;
        float* yi = y + (size_t)(2 * p + 1) * TLEN;
        #pragma unroll
        for (int n1 = 0; n1 < 8; n1++) {  // only n < T
            int n = n1 * 4096 + hi * 256 + tcol;
            yr[n] = v[n1].x;
            yi[n] = v[n1].y;
        }
        __syncthreads();  // WAR: protect sh before next tile
    }
}

extern "C" void kernel_launch(void* const* d_in, const int* in_sizes, int n_in,
                              void* d_out, int out_size) {
    const float* x = (const float*)d_in[0];
    const float* f = (const float*)d_in[1];
    float* y = (float*)d_out;

    k_colA<<<740, 256>>>(x, f);     // persistent: col fft16 + row stage-1 (+filter)
    k_filt_rowB<<<16, 256>>>();     // filter 256-FFT -> fp16 wf (x 1/65536)
    k_rowB<<<592, 256>>>();         // persistent: 256 fwd, *Wf, 256 inv
    k_colA_inv<<<740, 256>>>(y);    // persistent: undo-T1 + inv stages + y
}

// round 16
// speedup vs baseline: 1.1885x; 1.1885x over previous
#include <cuda_runtime.h>
#include <cuda_fp16.h>
#include <math.h>

#define TLEN 32768
#define NF   65536
#define TWO_PI 6.283185307179586476925f

// 128 complex signals x 65536 points, fp16 (re,im) packed = 32 MB scratch.
// Layout: g_work[p][k1*4096 + t1*256 + t]
__device__ __half2 g_work[128 * 65536];
// filter intermediate (fp32, after K1 filter branch, same layout as g_work)
__device__ float2 g_filt[65536];
// final filter spectrum (fp16, K2-register-matched, includes 1/65536)
__device__ __half2 g_wf[65536];

__device__ __forceinline__ float2 cmul(float2 a, float2 b) {
    return make_float2(fmaf(a.x, b.x, -(a.y * b.y)), fmaf(a.x, b.y, a.y * b.x));
}
__device__ __forceinline__ __half2 pack_h2(float2 a) { return __floats2half2_rn(a.x, a.y); }
__device__ __forceinline__ float2 unpack_h2(__half2 h) {
    float2 f = __half22float2(h);
    return make_float2(f.x, f.y);
}

// packed f32x2 add/sub (Blackwell): 1 instruction for a complex add/sub
__device__ __forceinline__ float2 f2add(float2 a, float2 b) {
    float2 c;
    asm("{\n\t.reg .b64 ra, rb, rc;\n\t"
        "mov.b64 ra, {%2, %3};\n\t"
        "mov.b64 rb, {%4, %5};\n\t"
        "add.rn.f32x2 rc, ra, rb;\n\t"
        "mov.b64 {%0, %1}, rc;\n\t}"
        : "=f"(c.x), "=f"(c.y)
        : "f"(a.x), "f"(a.y), "f"(b.x), "f"(b.y));
    return c;
}
__device__ __forceinline__ float2 f2sub(float2 a, float2 b) {
    float2 c;
    asm("{\n\t.reg .b64 ra, rb, rc;\n\t"
        "mov.b64 ra, {%2, %3};\n\t"
        "mov.b64 rb, {%4, %5};\n\t"
        "sub.rn.f32x2 rc, ra, rb;\n\t"
        "mov.b64 {%0, %1}, rc;\n\t}"
        : "=f"(c.x), "=f"(c.y)
        : "f"(a.x), "f"(a.y), "f"(b.x), "f"(b.y));
    return c;
}

template<int SIGN>
__device__ __forceinline__ void fft4(float2& a0, float2& a1, float2& a2, float2& a3) {
    float2 s0 = f2add(a0, a2);
    float2 d0 = f2sub(a0, a2);
    float2 s1 = f2add(a1, a3);
    float2 d1 = f2sub(a1, a3);
    float2 wd1 = (SIGN < 0) ? make_float2(d1.y, -d1.x) : make_float2(-d1.y, d1.x);
    a0 = f2add(s0, s1);
    a2 = f2sub(s0, s1);
    a1 = f2add(d0, wd1);
    a3 = f2sub(d0, wd1);
}

template<int SIGN>
__device__ __forceinline__ float2 w16f(int m) {
    const float C[10] = {1.f, 0.92387953251128675613f, 0.70710678118654752440f,
                         0.38268343236508977173f, 0.f, -0.38268343236508977173f,
                         -0.70710678118654752440f, -0.92387953251128675613f,
                         -1.f, -0.92387953251128675613f};
    const float S[10] = {0.f, 0.38268343236508977173f, 0.70710678118654752440f,
                         0.92387953251128675613f, 1.f, 0.92387953251128675613f,
                         0.70710678118654752440f, 0.38268343236508977173f,
                         0.f, -0.38268343236508977173f};
    return make_float2(C[m], (SIGN < 0) ? -S[m] : S[m]);
}

// 16-point DFT, natural-order in/out
template<int SIGN>
__device__ __forceinline__ void fft16(float2 v[16]) {
    #pragma unroll
    for (int b = 0; b < 4; b++) fft4<SIGN>(v[b], v[4 + b], v[8 + b], v[12 + b]);
    #pragma unroll
    for (int p = 1; p < 4; p++) {
        #pragma unroll
        for (int b = 1; b < 4; b++)
            v[4 * p + b] = cmul(v[4 * p + b], w16f<SIGN>(b * p));
    }
    #pragma unroll
    for (int p = 0; p < 4; p++) fft4<SIGN>(v[4 * p + 0], v[4 * p + 1], v[4 * p + 2], v[4 * p + 3]);
    float2 o[16];
    #pragma unroll
    for (int q = 0; q < 4; q++)
        #pragma unroll
        for (int p = 0; p < 4; p++) o[4 * q + p] = v[4 * p + q];
    #pragma unroll
    for (int i = 0; i < 16; i++) v[i] = o[i];
}

// v[k] *= t0 * w^k for k = 0..15, via 4 independent chains of 4 (log depth).
// UNIT=true: t0 == 1 (skips setup products and the v[0] multiply).
template<bool UNIT>
__device__ __forceinline__ void twmul16(float2 v[16], float2 t0, float2 w) {
    float2 t2 = cmul(w, w);
    float2 t4 = cmul(t2, t2);
    float2 t8 = cmul(t4, t4);
    float2 a, b, c, d;
    if (UNIT) { a = make_float2(1.f, 0.f); b = t4; c = t8; d = cmul(t4, t8); }
    else      { a = t0; b = cmul(t0, t4); c = cmul(t0, t8); d = cmul(b, t8); }
    #pragma unroll
    for (int i = 0; i < 4; i++) {
        if (!(UNIT && i == 0)) v[i] = cmul(v[i], a);
        v[4 + i]  = cmul(v[4 + i], b);
        v[8 + i]  = cmul(v[8 + i], c);
        v[12 + i] = cmul(v[12 + i], d);
        if (i < 3) {
            a = (UNIT && i == 0) ? w : cmul(a, w);
            b = cmul(b, w); c = cmul(c, w); d = cmul(d, w);
        }
    }
}

// 256-point DFT within one half-warp (group g = t>>4, lane l = t&15).
// wc = e^{SIGN*2pi i l/256} supplied by the caller (hoistable).
// Warp-private exchange (pad-17): write k1*17+l, read l*17+n2 — conflict-free.
template<int SIGN>
__device__ __forceinline__ void fft256_core(float2 v[16], int l, int g,
                                            float2* sh, float2 wc) {
    fft16<SIGN>(v);
    twmul16<true>(v, make_float2(1.f, 0.f), wc);
    __syncwarp();
    #pragma unroll
    for (int k1 = 0; k1 < 16; k1++)
        sh[g * 272 + k1 * 17 + l] = v[k1];
    __syncwarp();
    #pragma unroll
    for (int n2 = 0; n2 < 16; n2++)
        v[n2] = sh[g * 272 + l * 17 + n2];
    fft16<SIGN>(v);
}

// ======== K1 (fused): column fft16 + interstage twiddle + row stage-1 fft16
// + T1 twiddle. Signals: blocks 0..2047 (half2 out); filter: 2048..2063 ========
__global__ void __launch_bounds__(256) k_colA(const float* __restrict__ x,
                                              const float* __restrict__ f) {
    __shared__ float2 sh[16 * 272];
    int t = threadIdx.x;
    int hi = t >> 4, tl = t & 15;     // phase 1: hi = a; phase 2: hi = k1
    bool is_filt = (blockIdx.x >= 2048);
    int p = 0, tb;
    if (is_filt) tb = blockIdx.x - 2048;
    else { p = blockIdx.x >> 4; tb = blockIdx.x & 15; }
    int tcol = tb * 16 + tl;
    int n2 = hi * 256 + tcol;         // phase 1: hi = a
    float2 v[16];
    if (!is_filt) {
        const float* xr = x + (size_t)(2 * p) * TLEN;
        const float* xi = x + (size_t)(2 * p + 1) * TLEN;
        #pragma unroll
        for (int n1 = 0; n1 < 16; n1++) {
            if (n1 < 8) v[n1] = make_float2(xr[n1 * 4096 + n2], xi[n1 * 4096 + n2]);
            else v[n1] = make_float2(0.f, 0.f);
        }
    } else {
        #pragma unroll
        for (int n1 = 0; n1 < 16; n1++) {
            if (n1 < 8) v[n1] = make_float2(f[n1 * 4096 + n2], 0.f);
            else v[n1] = make_float2(0.f, 0.f);
        }
    }
    fft16<-1>(v);  // over n1 -> v[k1]
    // interstage twiddle e^{-2pi i n2 k1 / 65536}
    { float s, c; __sincosf(-TWO_PI * (float)n2 / 65536.0f, &s, &c);
      twmul16<true>(v, make_float2(1.f, 0.f), make_float2(c, s)); }
    // RT: (a, tl) holding all k1  ->  (k1, tl) holding all a
    #pragma unroll
    for (int k1 = 0; k1 < 16; k1++)
        sh[k1 * 272 + hi * 17 + tl] = v[k1];
    __syncthreads();
    #pragma unroll
    for (int a = 0; a < 16; a++)
        v[a] = sh[hi * 272 + a * 17 + tl];   // now hi = k1
    fft16<-1>(v);  // row stage-1 over a -> v[t1]
    // T1 twiddle e^{-2pi i tcol t1 / 4096}
    { float s, c; __sincosf(-TWO_PI * (float)tcol / 4096.0f, &s, &c);
      twmul16<true>(v, make_float2(1.f, 0.f), make_float2(c, s)); }
    if (!is_filt) {
        __half2* dst = g_work + (size_t)p * NF + hi * 4096;
        #pragma unroll
        for (int t1 = 0; t1 < 16; t1++)
            dst[t1 * 256 + tcol] = pack_h2(v[t1]);
    } else {
        float2* dst = g_filt + hi * 4096;
        #pragma unroll
        for (int t1 = 0; t1 < 16; t1++)
            dst[t1 * 256 + tcol] = v[t1];
    }
}

// ======== K0b: filter 256-pt row FFT -> fp16 wf (K2-matched, x 1/65536) ========
__global__ void __launch_bounds__(256) k_filt_rowB() {
    __shared__ float2 sh[16 * 272];
    int t = threadIdx.x;
    int g = t >> 4, l = t & 15;
    int k1 = blockIdx.x;
    float sv, cv; __sincosf(-TWO_PI * (float)l / 256.0f, &sv, &cv);
    const float2* basef = g_filt + k1 * 4096;
    float2 v[16];
    #pragma unroll
    for (int j = 0; j < 16; j++)
        v[j] = basef[g * 256 + 16 * j + l];
    fft256_core<-1>(v, l, g, sh, make_float2(cv, sv));
    const float inv = 1.0f / 65536.0f;
    #pragma unroll
    for (int u2 = 0; u2 < 16; u2++)
        g_wf[k1 * 4096 + u2 * 256 + t] =
            pack_h2(make_float2(v[u2].x * inv, v[u2].y * inv));
}

// ======== K2: 256-pt fwd -> *Wf -> 256-pt inv. No block barriers at all. ======
__global__ void __launch_bounds__(256) k_rowB() {
    __shared__ float2 sh[16 * 272];
    int t = threadIdx.x;
    int g = t >> 4, l = t & 15;
    int p = blockIdx.x >> 4, k1 = blockIdx.x & 15;
    float sv, cv; __sincosf(-TWO_PI * (float)l / 256.0f, &sv, &cv);
    float2 wfw = make_float2(cv, sv);    // forward core twiddle base
    float2 wiv = make_float2(cv, -sv);   // inverse core twiddle base (conj)
    __half2* base = g_work + (size_t)p * NF + k1 * 4096;
    const __half2* __restrict__ wfh = g_wf + k1 * 4096;
    float2 v[16];
    #pragma unroll
    for (int j = 0; j < 16; j++)
        v[j] = unpack_h2(base[g * 256 + 16 * j + l]);
    fft256_core<-1>(v, l, g, sh, wfw);
    #pragma unroll
    for (int u2 = 0; u2 < 16; u2++)
        v[u2] = cmul(v[u2], unpack_h2(wfh[u2 * 256 + t]));
    fft256_core<1>(v, l, g, sh, wiv);
    #pragma unroll
    for (int sg = 0; sg < 16; sg++)
        base[g * 256 + 16 * sg + l] = pack_h2(v[sg]);
}

// ======== K3: undo-T1 + row stage-1 inverse fft16 + conj interstage +
// column inverse fft16 + write y ========
__global__ void __launch_bounds__(256) k_colA_inv(float* __restrict__ y) {
    __shared__ float2 sh[16 * 272];
    int t = threadIdx.x;
    int hi = t >> 4, tl = t & 15;     // phase 1: hi = k1; phase 2: hi = a
    int p = blockIdx.x >> 4, tb = blockIdx.x & 15;
    int tcol = tb * 16 + tl;
    const __half2* src = g_work + (size_t)p * NF;
    float2 v[16];
    #pragma unroll
    for (int t1 = 0; t1 < 16; t1++)
        v[t1] = unpack_h2(src[hi * 4096 + t1 * 256 + tcol]);   // hi = k1
    // undo T1: e^{+2pi i tcol t1 / 4096}
    { float s, c; __sincosf(TWO_PI * (float)tcol / 4096.0f, &s, &c);
      twmul16<true>(v, make_float2(1.f, 0.f), make_float2(c, s)); }
    fft16<1>(v);  // over t1 -> v[a] = z_row[a*256 + tcol]
    // conj interstage: omegaN^{+(a*256+tcol)*k1} over a
    { float s0, c0; __sincosf(TWO_PI * (float)(tcol * hi) / 65536.0f, &s0, &c0);
      float sw, cw; __sincosf(TWO_PI * (float)hi / 256.0f, &sw, &cw);
      twmul16<false>(v, make_float2(c0, s0), make_float2(cw, sw)); }
    // RT: (k1, tl) holding all a  ->  (a, tl) holding all k1
    #pragma unroll
    for (int a = 0; a < 16; a++)
        sh[a * 272 + hi * 17 + tl] = v[a];
    __syncthreads();
    #pragma unroll
    for (int k1 = 0; k1 < 16; k1++)
        v[k1] = sh[hi * 272 + k1 * 17 + tl];   // now hi = a
    fft16<1>(v);  // over k1 -> v[n1]
    float* yr = y + (size_t)(2 * p) * TLEN;
    float* yi = y + (size_t)(2 * p + 1) * TLEN;
    #pragma unroll
    for (int n1 = 0; n1 < 8; n1++) {  // only n < T
        int n = n1 * 4096 + hi * 256 + tcol;
        yr[n] = v[n1].x;
        yi[n] = v[n1].y;
    }
}

extern "C" void kernel_launch(void* const* d_in, const int* in_sizes, int n_in,
                              void* d_out, int out_size) {
    const float* x = (const float*)d_in[0];
    const float* f = (const float*)d_in[1];
    float* y = (float*)d_out;

    k_colA<<<2064, 256>>>(x, f);    // col fft16 + row stage-1 (+ filter)
    k_filt_rowB<<<16, 256>>>();     // filter 256-FFT -> fp16 wf (x 1/65536)
    k_rowB<<<2048, 256>>>();        // 256 fwd, *Wf, 256 inv (no barriers)
    k_colA_inv<<<2048, 256>>>(y);   // undo-T1 + stage-1 inv + col inv + y
}